// round 1
// baseline (speedup 1.0000x reference)
#include <cuda_runtime.h>
#include <cuda_bf16.h>

// Problem constants
#define N_E    1024
#define N_IN   64
#define HID    128
#define OUTD   64
#define IPB    8          // i-rows per block (kernel 2 and kernel 1)
#define TP     64         // B-rows per shared tile in kernel 2

// Scratch for factored pre-activations (allowed: static __device__ arrays)
__device__ float g_A[N_E * HID];   // x @ W1[:64]  + b1   (b1 folded in)
__device__ float g_B[N_E * HID];   // x @ W1[64:]

__device__ __forceinline__ float tanh_fast(float x) {
    float y;
    asm("tanh.approx.f32 %0, %1;" : "=f"(y) : "f"(x));
    return y;
}

// ---------------------------------------------------------------------------
// Kernel 1: A[i][h] = sum_f x[i][f]*W1[f][h] + b1[h];  B[i][h] = sum_f x[i][f]*W1[64+f][h]
// grid = 128 blocks, 128 threads (thread = hidden unit h), 8 i-rows per block.
// ---------------------------------------------------------------------------
__global__ void __launch_bounds__(HID) pre_kernel(const float* __restrict__ x,
                                                  const float* __restrict__ W1,
                                                  const float* __restrict__ b1) {
    const int h  = threadIdx.x;
    const int i0 = blockIdx.x * IPB;

    __shared__ float xs[IPB * N_IN];   // 8 x 64 floats = 2KB
    for (int idx = threadIdx.x; idx < IPB * N_IN; idx += HID)
        xs[idx] = x[i0 * N_IN + idx];
    __syncthreads();

    float a[IPB], b[IPB];
    const float bb1 = b1[h];
    #pragma unroll
    for (int k = 0; k < IPB; k++) { a[k] = bb1; b[k] = 0.0f; }

    #pragma unroll 4
    for (int f = 0; f < N_IN; f++) {
        const float wa = W1[f * HID + h];           // coalesced across h
        const float wb = W1[(f + N_IN) * HID + h];
        #pragma unroll
        for (int k = 0; k < IPB; k++) {
            const float xv = xs[k * N_IN + f];      // broadcast within warp
            a[k] = fmaf(xv, wa, a[k]);
            b[k] = fmaf(xv, wb, b[k]);
        }
    }

    #pragma unroll
    for (int k = 0; k < IPB; k++) {
        g_A[(i0 + k) * HID + h] = a[k];
        g_B[(i0 + k) * HID + h] = b[k];
    }
}

// ---------------------------------------------------------------------------
// Kernel 2: the MUFU-bound partner loop + W2 epilogue.
// grid = 128 blocks, 128 threads. Thread h owns hidden unit h for 8 i-rows.
//   S[i][h] = sum_{p=0..1023} tanh(A[i][h] + B[p][h])  - tanh(A[i][h] + B[i][h])
//   out[i][o] = (S[i][:] . W2[:,o]) / 1023 + b2[o]
// ---------------------------------------------------------------------------
__global__ void __launch_bounds__(HID) pair_kernel(const float* __restrict__ W2,
                                                   const float* __restrict__ b2,
                                                   float* __restrict__ out) {
    const int h  = threadIdx.x;
    const int i0 = blockIdx.x * IPB;

    __shared__ float sh[TP * HID];     // 64 x 128 floats = 32KB B tile (reused for S)

    float a[IPB], s[IPB];
    #pragma unroll
    for (int k = 0; k < IPB; k++) {
        a[k] = g_A[(i0 + k) * HID + h];
        s[k] = 0.0f;
    }

    for (int tile = 0; tile < N_E; tile += TP) {
        __syncthreads();
        // Stage TP rows of B into shared (float4, coalesced)
        const float4* src = (const float4*)(g_B + tile * HID);
        float4* dst = (float4*)sh;
        #pragma unroll
        for (int idx = threadIdx.x; idx < TP * (HID / 4); idx += HID)
            dst[idx] = src[idx];
        __syncthreads();

        #pragma unroll 4
        for (int p = 0; p < TP; p++) {
            const float bp = sh[p * HID + h];   // stride-1 across warp: conflict-free
            #pragma unroll
            for (int k = 0; k < IPB; k++)
                s[k] += tanh_fast(a[k] + bp);   // 8 independent MUFU chains
        }
    }

    // Subtract self term (p == i was included above)
    #pragma unroll
    for (int k = 0; k < IPB; k++)
        s[k] -= tanh_fast(a[k] + g_B[(i0 + k) * HID + h]);

    // Epilogue: out[i0+k][o] = (S . W2[:,o]) / 1023 + b2[o]
    __syncthreads();
    #pragma unroll
    for (int k = 0; k < IPB; k++)
        sh[k * HID + h] = s[k];                 // S tile: 8 x 128
    __syncthreads();

    const int o = threadIdx.x & (OUTD - 1);     // 0..63
    const int g = threadIdx.x >> 6;             // 0..1
    float acc[4];
    #pragma unroll
    for (int kk = 0; kk < 4; kk++) acc[kk] = 0.0f;

    #pragma unroll 4
    for (int hh = 0; hh < HID; hh++) {
        const float w = W2[hh * OUTD + o];      // coalesced across o
        #pragma unroll
        for (int kk = 0; kk < 4; kk++)
            acc[kk] = fmaf(sh[(g + kk * 2) * HID + hh], w, acc[kk]);
    }

    const float bb2 = b2[o];
    #pragma unroll
    for (int kk = 0; kk < 4; kk++)
        out[(i0 + g + kk * 2) * OUTD + o] = acc[kk] * (1.0f / 1023.0f) + bb2;
}

// ---------------------------------------------------------------------------
extern "C" void kernel_launch(void* const* d_in, const int* in_sizes, int n_in,
                              void* d_out, int out_size) {
    const float* x  = (const float*)d_in[0];   // [1024, 64]
    const float* W1 = (const float*)d_in[1];   // [128, 128]
    const float* b1 = (const float*)d_in[2];   // [128]
    const float* W2 = (const float*)d_in[3];   // [128, 64]
    const float* b2 = (const float*)d_in[4];   // [64]
    float* out = (float*)d_out;                // [1024, 64]

    pre_kernel<<<N_E / IPB, HID>>>(x, W1, b1);
    pair_kernel<<<N_E / IPB, HID>>>(W2, b2, out);
}

// round 2
// speedup vs baseline: 1.0951x; 1.0951x over previous
#include <cuda_runtime.h>
#include <cuda_bf16.h>

// Problem constants
#define N_E    1024
#define N_IN   64
#define HID    128
#define OUTD   64
#define IPB    8          // i-rows per block
#define TP     32         // B-rows per shared tile PER HALF (2 halves resident)
#define NTHR   256        // 8 warps -> 2 warps per SMSP

// Scratch for factored pre-activations
__device__ float g_A[N_E * HID];   // x @ W1[:64]  + b1   (b1 folded in)
__device__ float g_B[N_E * HID];   // x @ W1[64:]

__device__ __forceinline__ float tanh_fast(float x) {
    float y;
    asm("tanh.approx.f32 %0, %1;" : "=f"(y) : "f"(x));
    return y;
}

// ---------------------------------------------------------------------------
// Kernel 1: A[i][h] = sum_f x[i][f]*W1[f][h] + b1[h];  B[i][h] = sum_f x[i][f]*W1[64+f][h]
// ---------------------------------------------------------------------------
__global__ void __launch_bounds__(HID) pre_kernel(const float* __restrict__ x,
                                                  const float* __restrict__ W1,
                                                  const float* __restrict__ b1) {
    const int h  = threadIdx.x;
    const int i0 = blockIdx.x * IPB;

    __shared__ float xs[IPB * N_IN];
    for (int idx = threadIdx.x; idx < IPB * N_IN; idx += HID)
        xs[idx] = x[i0 * N_IN + idx];
    __syncthreads();

    float a[IPB], b[IPB];
    const float bb1 = b1[h];
    #pragma unroll
    for (int k = 0; k < IPB; k++) { a[k] = bb1; b[k] = 0.0f; }

    #pragma unroll 4
    for (int f = 0; f < N_IN; f++) {
        const float wa = W1[f * HID + h];
        const float wb = W1[(f + N_IN) * HID + h];
        #pragma unroll
        for (int k = 0; k < IPB; k++) {
            const float xv = xs[k * N_IN + f];
            a[k] = fmaf(xv, wa, a[k]);
            b[k] = fmaf(xv, wb, b[k]);
        }
    }

    #pragma unroll
    for (int k = 0; k < IPB; k++) {
        g_A[(i0 + k) * HID + h] = a[k];
        g_B[(i0 + k) * HID + h] = b[k];
    }
}

// ---------------------------------------------------------------------------
// Kernel 2: MUFU-bound partner loop, 256 threads (2 warps/SMSP).
// Thread = (h, half). half 0 handles p in [0,512), half 1 handles [512,1024).
//   S[i][h] = sum_p tanh(A[i][h] + B[p][h]) - tanh(A[i][h] + B[i][h])
//   out[i][o] = (S[i][:] . W2[:,o]) / 1023 + b2[o]
// ---------------------------------------------------------------------------
__global__ void __launch_bounds__(NTHR) pair_kernel(const float* __restrict__ W2,
                                                    const float* __restrict__ b2,
                                                    float* __restrict__ out) {
    const int tid  = threadIdx.x;
    const int h    = tid & (HID - 1);
    const int half = tid >> 7;            // 0 or 1
    const int i0   = blockIdx.x * IPB;

    __shared__ float sh[2 * TP * HID];    // 2 x 32 x 128 floats = 32KB

    float a[IPB], s[IPB];
    #pragma unroll
    for (int k = 0; k < IPB; k++) {
        a[k] = g_A[(i0 + k) * HID + h];
        s[k] = 0.0f;
    }

    const int p_base   = half * (N_E / 2);          // 0 or 512
    float* my_sh       = sh + half * TP * HID;

    for (int tile = 0; tile < N_E / 2; tile += TP) {
        __syncthreads();
        // Each half stages its own TP x 128 B tile (float4, coalesced)
        const float4* src = (const float4*)(g_B + (p_base + tile) * HID);
        float4* dst = (float4*)my_sh;
        #pragma unroll
        for (int idx = h; idx < TP * (HID / 4); idx += HID)
            dst[idx] = src[idx];
        __syncthreads();

        #pragma unroll 4
        for (int p = 0; p < TP; p++) {
            const float bp = my_sh[p * HID + h];    // conflict-free across warp
            #pragma unroll
            for (int k = 0; k < IPB; k++)
                s[k] += tanh_fast(a[k] + bp);       // 8 independent MUFU chains
        }
    }

    // Combine halves through shared, subtract self term, stage S for epilogue
    __syncthreads();
    if (half == 1) {
        #pragma unroll
        for (int k = 0; k < IPB; k++)
            sh[k * HID + h] = s[k];
    }
    __syncthreads();
    if (half == 0) {
        #pragma unroll
        for (int k = 0; k < IPB; k++) {
            float tot = s[k] + sh[k * HID + h];
            tot -= tanh_fast(a[k] + g_B[(i0 + k) * HID + h]);   // remove p==i
            s[k] = tot;
        }
    }
    __syncthreads();
    if (half == 0) {
        #pragma unroll
        for (int k = 0; k < IPB; k++)
            sh[k * HID + h] = s[k];               // final S tile: 8 x 128
    }
    __syncthreads();

    // Epilogue: out[i0+r][o] = (S[r] . W2[:,o]) / 1023 + b2[o]
    // 256 threads: o = tid&63 (0..63), g = tid>>6 (0..3); rows g and g+4 per thread.
    const int o = tid & (OUTD - 1);
    const int g = tid >> 6;
    float acc0 = 0.0f, acc1 = 0.0f;

    #pragma unroll 4
    for (int hh = 0; hh < HID; hh++) {
        const float w = W2[hh * OUTD + o];        // coalesced across o
        acc0 = fmaf(sh[g       * HID + hh], w, acc0);
        acc1 = fmaf(sh[(g + 4) * HID + hh], w, acc1);
    }

    const float bb2 = b2[o];
    out[(i0 + g    ) * OUTD + o] = acc0 * (1.0f / 1023.0f) + bb2;
    out[(i0 + g + 4) * OUTD + o] = acc1 * (1.0f / 1023.0f) + bb2;
}

// ---------------------------------------------------------------------------
extern "C" void kernel_launch(void* const* d_in, const int* in_sizes, int n_in,
                              void* d_out, int out_size) {
    const float* x  = (const float*)d_in[0];   // [1024, 64]
    const float* W1 = (const float*)d_in[1];   // [128, 128]
    const float* b1 = (const float*)d_in[2];   // [128]
    const float* W2 = (const float*)d_in[3];   // [128, 64]
    const float* b2 = (const float*)d_in[4];   // [64]
    float* out = (float*)d_out;                // [1024, 64]

    pre_kernel<<<N_E / IPB, HID>>>(x, W1, b1);
    pair_kernel<<<N_E / IPB, NTHR>>>(W2, b2, out);
}